// round 5
// baseline (speedup 1.0000x reference)
#include <cuda_runtime.h>

#define BDIM  256
#define CHUNK 4096
#define FTAPS 16
#define NLEN  131072

__global__ __launch_bounds__(BDIM)
void fir2_kernel(const float* __restrict__ x,
                 const float* __restrict__ kern,
                 float* __restrict__ out) {
    __shared__ __align__(16) float xs[CHUNK + 32];   // x[chunkStart-32 .. chunkStart+CHUNK)
    __shared__ __align__(16) float vs[CHUNK + 16];   // v[chunkStart-16 .. chunkStart+CHUNK)
    __shared__ float hsm[FTAPS];

    const int tid = threadIdx.x;
    const int row = blockIdx.y;
    const long chunkStart = (long)blockIdx.x * CHUNK;
    const float* xrow = x + (size_t)row * NLEN;
    float* orow = out + (size_t)row * NLEN;

    if (tid < FTAPS) hsm[tid] = kern[tid];

    // ---- cooperative load of x tile + 32-left halo (vectorized) ----
    {
        const long gbase = chunkStart - 32;
        #pragma unroll 2
        for (int i = tid; i < (CHUNK + 32) / 4; i += BDIM) {
            long g = gbase + 4L * i;               // multiple of 4 -> whole vec in/out of range
            float4 val = make_float4(0.f, 0.f, 0.f, 0.f);
            if (g >= 0) val = *(const float4*)(xrow + g);
            ((float4*)xs)[i] = val;
        }
    }
    __syncthreads();

    float h[FTAPS];
    #pragma unroll
    for (int j = 0; j < FTAPS; j++) h[j] = hsm[j];   // broadcast LDS, conflict-free

    // ---- v stage: local l in [0, CHUNK+16), global gv = chunkStart - 16 + l
    //      v[l] = xs[l+16] + sum_{m=0..15} h[15-m] * xs[l+m]
    for (int g = tid; g < (CHUNK + 16) / 8; g += BDIM) {
        const int base = g * 8;
        __align__(16) float w[24];
        #pragma unroll
        for (int q = 0; q < 6; q++)
            ((float4*)w)[q] = *(const float4*)&xs[base + 4 * q];

        __align__(16) float acc[8];
        #pragma unroll
        for (int e = 0; e < 8; e++) {
            float a = w[e + 16];
            #pragma unroll
            for (int m = 0; m < FTAPS; m++)
                a = fmaf(h[15 - m], w[e + m], a);
            long gv = chunkStart - 16 + base + e;
            acc[e] = (gv >= FTAPS) ? a : 0.f;
        }
        #pragma unroll
        for (int q = 0; q < 2; q++)
            ((float4*)&vs[base])[q] = ((float4*)acc)[q];
    }
    __syncthreads();

    // ---- y stage: local i in [0, CHUNK), global gy = chunkStart + i
    //      y[i] = vs[i+16] + sum_{m=0..15} h[m] * vs[i+m]
    for (int g = tid; g < CHUNK / 8; g += BDIM) {
        const int base = g * 8;
        __align__(16) float w[24];
        #pragma unroll
        for (int q = 0; q < 6; q++)
            ((float4*)w)[q] = *(const float4*)&vs[base + 4 * q];

        __align__(16) float acc[8];
        #pragma unroll
        for (int e = 0; e < 8; e++) {
            float a = w[e + 16];
            #pragma unroll
            for (int m = 0; m < FTAPS; m++)
                a = fmaf(h[m], w[e + m], a);
            long gy = chunkStart + base + e;
            acc[e] = (gy >= FTAPS) ? a : 0.f;
        }
        #pragma unroll
        for (int q = 0; q < 2; q++)
            *(float4*)(orow + chunkStart + base + 4 * q) = ((float4*)acc)[q];
    }
}

extern "C" void kernel_launch(void* const* d_in, const int* in_sizes, int n_in,
                              void* d_out, int out_size) {
    const float* x    = (const float*)d_in[0];   // (256, 131072) f32
    const float* kern = (const float*)d_in[1];   // (1, 16) f32
    float* out        = (float*)d_out;

    dim3 grid(NLEN / CHUNK, 256, 1);             // 32 x 256 = 8192 CTAs
    fir2_kernel<<<grid, BDIM>>>(x, kern, out);
}